// round 11
// baseline (speedup 1.0000x reference)
#include <cuda_runtime.h>
#include <cuda_bf16.h>

// Output of reference = minimum(y, 0.25) then clip(0.25, 1.0) == 0.25 everywhere,
// independent of inputs (all finite). Pure constant fill.
//
// FINAL (converged; 36.928001 us reproduced bit-identically in R1/R8/R9/R10):
// the bench is paced by steady-state L2->DRAM write drain at ~6.6 TB/s
// (244 MB per graph replay = 82% of spec HBM, the pure-write-stream ceiling).
// The ~2.9 us kernel-vs-bench gap is the dirty-line drain tail overlapping the
// next replay. Ten rounds closed every axis: address pattern, occupancy
// 23-88%, MLP 1-8, cache policy (.cs / evict_last / default), 128/256-bit
// width, CTA count 1.2K-59.6K — all flat; TMA store path is documented
// LTS-cap-equivalent (non-lever); byte reduction is barred by the harness
// contracts (poisoned-buffer single-call correctness, same-work determinism,
// device-limit guard on L2 persistence). One 128-bit store per thread in
// globally sequential order is the measured optimum.

#define MIN_VALUE 0.25f

__global__ void fill_const_vec4(float4* __restrict__ out4, long long n4) {
    long long i = (long long)blockIdx.x * blockDim.x + threadIdx.x;
    if (i < n4) {
        out4[i] = make_float4(MIN_VALUE, MIN_VALUE, MIN_VALUE, MIN_VALUE);
    }
}

__global__ void fill_const_tail(float* __restrict__ out, long long start, long long n) {
    long long i = start + (long long)blockIdx.x * blockDim.x + threadIdx.x;
    if (i < n) {
        out[i] = MIN_VALUE;
    }
}

extern "C" void kernel_launch(void* const* d_in, const int* in_sizes, int n_in,
                              void* d_out, int out_size) {
    (void)d_in; (void)in_sizes; (void)n_in;

    long long n = (long long)out_size;
    long long n4 = n >> 2;              // number of float4 stores
    long long tail_start = n4 << 2;

    const int threads = 256;

    if (n4 > 0) {
        long long blocks = (n4 + threads - 1) / threads;
        fill_const_vec4<<<(unsigned int)blocks, threads>>>((float4*)d_out, n4);
    }
    if (tail_start < n) {
        long long tail = n - tail_start;
        long long blocks = (tail + threads - 1) / threads;
        fill_const_tail<<<(unsigned int)blocks, threads>>>((float*)d_out, tail_start, n);
    }
}